// round 12
// baseline (speedup 1.0000x reference)
#include <cuda_runtime.h>

// SSIM loss, 7x7 valid window, [32,3,512,512] fp32, scalar out.
// R12 = R11 with the half-0 window fix: f4 offsets {0,1,2,3,5} (skip the
// pad at f2 8,9; f2 10,11 are the next group's first data columns).
// One 1024-thread CTA (1 CTA/SM), 8-row double-buffered subchunks.
// Threads 0-511: vertical running column sums (register ring, prefetch-8).
// Threads 512-1023: horizontal, 8 outputs each (two 4-col halves over a
// shared GS=10 padded group). Mixed roles per SMSP hide LDG latency.

#define IW     512
#define OH     506
#define OW     506
#define BR     88
#define NBANDS 6
#define NIMG   96
#define NCTA   (NBANDS * NIMG)      // 576
#define GS     10                   // f2 per group: 8 data + 2 pad
#define ROWF2  640                  // 64 groups * 10
#define PLANEF2 (8 * ROWF2)         // 5120 (8 rows)
#define BUFF2  (2 * PLANEF2)        // 10240
#define SMEM_F2 (2 * BUFF2 + 16)
#define SMEM_BYTES (SMEM_F2 * 8)    // 163,968 B -> 1 CTA/SM

typedef unsigned long long u64;

__device__ float g_partials[NCTA];
__device__ unsigned int g_count = 0;

__device__ __forceinline__ u64 add2(u64 a, u64 b) {
    u64 r; asm("add.rn.f32x2 %0, %1, %2;" : "=l"(r) : "l"(a), "l"(b)); return r;
}
__device__ __forceinline__ u64 fma2(u64 a, u64 b, u64 c) {
    u64 r; asm("fma.rn.f32x2 %0, %1, %2, %3;" : "=l"(r) : "l"(a), "l"(b), "l"(c)); return r;
}
__device__ __forceinline__ void unpack2(u64 v, float& a, float& b) {
    asm("mov.b64 {%0, %1}, %2;" : "=f"(a), "=f"(b) : "l"(v));
}
#define NEG1X2 0xBF800000BF800000ull

__device__ __forceinline__ void block_bar() {
    asm volatile("bar.sync 0, 1024;" ::: "memory");
}

__device__ __forceinline__ float ssim_term(float sx, float sy, float ss, float sxy) {
    const float c1big = 0.2401f;   // 2401 * (0.01)^2
    const float c2big = 2.1168f;   // 2352 * (0.03)^2
    float t1 = sx * sy;
    float a1 = fmaf(t1, 2.0f, c1big);
    float b1 = fmaf(sx, sx, c1big);
    b1 = fmaf(sy, sy, b1);
    float a2 = fmaf(sxy, 98.0f, c2big);
    a2 = fmaf(t1, -2.0f, a2);
    float b2 = fmaf(ss, 49.0f, c2big);
    b2 = fmaf(sx, -sx, b2);
    b2 = fmaf(sy, -sy, b2);
    return __fdividef(a1 * a2, b1 * b2);
}

struct VState {
    float Vx, Vy, Vs, Vxy;
    float rx[8], ry[8];   // ring: slot j holds the row subtracted at step j
};

template <bool GUARD>
__device__ __forceinline__ void prefetch8(
    const float* __restrict__ xp, const float* __restrict__ yp,
    float* nx, float* ny, int rb, int rmax, int col) {
#pragma unroll
    for (int j = 0; j < 8; ++j) {
        if (!GUARD || rb + j <= rmax) {
            nx[j] = xp[(size_t)(rb + j + 6) * IW + col];
            ny[j] = yp[(size_t)(rb + j + 6) * IW + col];
        }
    }
}

// Vertical: 8 rows (rb % 8 == 0), per-column running sums; ring period = 8.
template <bool GUARD>
__device__ __forceinline__ void vert8(
    VState& v, float2* __restrict__ buf, const float* nx, const float* ny,
    int rb, int rmax, int sidx) {
#pragma unroll
    for (int j = 0; j < 8; ++j) {
        if (!GUARD || rb + j <= rmax) {
            float xn = nx[j], yn = ny[j];
            v.Vx += xn; v.Vy += yn;
            v.Vs  = fmaf(xn, xn, v.Vs);
            v.Vs  = fmaf(yn, yn, v.Vs);
            v.Vxy = fmaf(xn, yn, v.Vxy);
            buf[j * ROWF2 + sidx]           = make_float2(v.Vx, v.Vy);
            buf[PLANEF2 + j * ROWF2 + sidx] = make_float2(v.Vs, v.Vxy);
            float xo = v.rx[j];
            float yo = v.ry[j];
            v.Vx -= xo; v.Vy -= yo;
            v.Vs  = fmaf(xo, -xo, v.Vs);
            v.Vs  = fmaf(yo, -yo, v.Vs);
            v.Vxy = fmaf(xo, -yo, v.Vxy);
            v.rx[(j + 6) & 7] = xn;
            v.ry[(j + 6) & 7] = yn;
        }
    }
}

// 4-output sliding window + ssim from two 10-wide window reg arrays.
__device__ __forceinline__ void win4(
    const u64* wa, const u64* wb, int c0, float& acc) {
    u64 Bout[4];
    {
        u64 B = wa[0];
#pragma unroll
        for (int k = 1; k < 7; ++k) B = add2(B, wa[k]);
        Bout[0] = B;
#pragma unroll
        for (int i = 1; i < 4; ++i) {
            B = add2(B, wa[i + 6]);
            B = fma2(wa[i - 1], NEG1X2, B);
            Bout[i] = B;
        }
    }
    const int T = (OW - c0 < 4) ? (OW - c0) : 4;
    u64 B = wb[0];
#pragma unroll
    for (int k = 1; k < 7; ++k) B = add2(B, wb[k]);
    {
        float sx, sy, ss, sxy;
        unpack2(Bout[0], sx, sy); unpack2(B, ss, sxy);
        acc += ssim_term(sx, sy, ss, sxy);
    }
#pragma unroll
    for (int i = 1; i < 4; ++i) {
        B = add2(B, wb[i + 6]);
        B = fma2(wb[i - 1], NEG1X2, B);
        if (i < T) {
            float sx, sy, ss, sxy;
            unpack2(Bout[i], sx, sy); unpack2(B, ss, sxy);
            acc += ssim_term(sx, sy, ss, sxy);
        }
    }
}

// Load 10 window values (f2 units) from 5 LDS.128.
__device__ __forceinline__ void loadw(
    ulonglong2 t0, ulonglong2 t1, ulonglong2 t2, ulonglong2 t3, ulonglong2 t4,
    u64* w) {
    w[0] = t0.x; w[1] = t0.y; w[2] = t1.x; w[3] = t1.y;
    w[4] = t2.x; w[5] = t2.y; w[6] = t3.x; w[7] = t3.y;
    w[8] = t4.x; w[9] = t4.y;
}

// Horizontal: 8 outputs = two 4-col halves over one GS=10 group.
template <bool GUARD>
__device__ __forceinline__ void horiz8x(
    const float2* __restrict__ sb, int rb, int rmax,
    int jrow, int G, float& acc) {
    if (GUARD && rb + jrow > rmax) return;
    const ulonglong2* pA = (const ulonglong2*)(sb + jrow * ROWF2 + GS * G);
    const ulonglong2* pB = (const ulonglong2*)(sb + PLANEF2 + jrow * ROWF2 + GS * G);

    // half 0: cols 8G..8G+3, window f2 {0..7,10,11} = f4 {0,1,2,3,5}
    {
        u64 wa[10], wb[10];
        loadw(pA[0], pA[1], pA[2], pA[3], pA[5], wa);
        loadw(pB[0], pB[1], pB[2], pB[3], pB[5], wb);
        win4(wa, wb, 8 * G, acc);
    }
    // half 1: cols 8G+4..8G+7, window f2 {4..7,10..15} = f4 {2,3,5,6,7}
    if (8 * G + 4 < OW) {
        u64 wa[10], wb[10];
        loadw(pA[2], pA[3], pA[5], pA[6], pA[7], wa);
        loadw(pB[2], pB[3], pB[5], pB[6], pB[7], wb);
        win4(wa, wb, 8 * G + 4, acc);
    }
}

template <bool GUARD>
__device__ __forceinline__ float band_loop(
    const float* __restrict__ xp, const float* __restrict__ yp,
    float2* __restrict__ sm, int r0, int rmax, int tid) {

    const int nsub = GUARD ? (((rmax - r0) >> 3) + 1) : (BR / 8);
    float acc = 0.f;

    if (tid < 512) {
        // -------- vertical half --------
        const int col  = tid;
        const int sidx = GS * (col >> 3) + (col & 7);

        VState v;
        v.Vx = 0.f; v.Vy = 0.f; v.Vs = 0.f; v.Vxy = 0.f;
        // prologue rows r0..r0+5 -> ring slots 0..5
#pragma unroll
        for (int k = 0; k < 6; ++k) {
            float x = xp[(size_t)(r0 + k) * IW + col];
            float y = yp[(size_t)(r0 + k) * IW + col];
            v.Vx += x; v.Vy += y;
            v.Vs  = fmaf(x, x, v.Vs);
            v.Vs  = fmaf(y, y, v.Vs);
            v.Vxy = fmaf(x, y, v.Vxy);
            v.rx[k] = x; v.ry[k] = y;
        }
        {   // subchunk 0 (rows r0..r0+7, always valid)
            float nx[8], ny[8];
            prefetch8<false>(xp, yp, nx, ny, r0, rmax, col);
            vert8<false>(v, sm, nx, ny, r0, rmax, sidx);
        }
        block_bar();
        for (int t = 0; t < nsub; ++t) {
            if (t + 1 < nsub) {
                const int rbn = r0 + 8 * (t + 1);
                float nx[8], ny[8];
                prefetch8<GUARD>(xp, yp, nx, ny, rbn, rmax, col);
                vert8<GUARD>(v, sm + (size_t)((t + 1) & 1) * BUFF2,
                             nx, ny, rbn, rmax, sidx);
            }
            block_bar();
        }
    } else {
        // -------- horizontal half --------
        const int ht   = tid - 512;
        const int jrow = ht >> 6;   // 0..7
        const int G    = ht & 63;   // 0..63
        block_bar();
        for (int t = 0; t < nsub; ++t) {
            horiz8x<GUARD>(sm + (size_t)(t & 1) * BUFF2, r0 + 8 * t,
                           rmax, jrow, G, acc);
            block_bar();
        }
    }
    return acc;
}

__global__ __launch_bounds__(1024, 1)
void ssim_kernel(const float* __restrict__ X, const float* __restrict__ Y,
                 float* __restrict__ out) {
    extern __shared__ float2 smbuf[];
    __shared__ float wsum[32];
    __shared__ bool isLast;

    const int tid  = threadIdx.x;
    const int band = blockIdx.x;
    const int img  = blockIdx.y;

    const float* __restrict__ xp = X + (size_t)img * (512 * 512);
    const float* __restrict__ yp = Y + (size_t)img * (512 * 512);
    const int r0   = band * BR;
    const int rmax = min(r0 + BR - 1, OH - 1);

    float acc;
    if (rmax == r0 + BR - 1) {
        acc = band_loop<false>(xp, yp, smbuf, r0, rmax, tid);
    } else {
        acc = band_loop<true>(xp, yp, smbuf, r0, rmax, tid);
    }

    // ---- block reduction ----
#pragma unroll
    for (int o = 16; o > 0; o >>= 1)
        acc += __shfl_xor_sync(0xffffffffu, acc, o);
    if ((tid & 31) == 0) wsum[tid >> 5] = acc;
    __syncthreads();

    if (tid == 0) {
        float s = 0.f;
#pragma unroll
        for (int w = 0; w < 32; ++w) s += wsum[w];
        g_partials[img * NBANDS + band] = s;
        __threadfence();
        unsigned int old = atomicAdd(&g_count, 1u);
        isLast = (old == NCTA - 1);
    }
    __syncthreads();

    // ---- deterministic last-block global reduction ----
    if (isLast) {
        float s = 0.f;
        for (int i = tid; i < NCTA; i += 1024) s += g_partials[i];
#pragma unroll
        for (int o = 16; o > 0; o >>= 1)
            s += __shfl_xor_sync(0xffffffffu, s, o);
        if ((tid & 31) == 0) wsum[tid >> 5] = s;
        __syncthreads();
        if (tid == 0) {
            float t = 0.f;
#pragma unroll
            for (int w = 0; w < 32; ++w) t += wsum[w];
            out[0] = 1.0f - t * (1.0f / 24579456.0f);  // 96*506*506
            g_count = 0;  // reset for next graph replay
        }
    }
}

extern "C" void kernel_launch(void* const* d_in, const int* in_sizes, int n_in,
                              void* d_out, int out_size) {
    (void)in_sizes; (void)n_in; (void)out_size;
    const float* X = (const float*)d_in[0];
    const float* Y = (const float*)d_in[1];

    cudaFuncSetAttribute(ssim_kernel,
                         cudaFuncAttributeMaxDynamicSharedMemorySize, SMEM_BYTES);

    dim3 grid(NBANDS, NIMG);
    ssim_kernel<<<grid, 1024, SMEM_BYTES>>>(X, Y, (float*)d_out);
}

// round 13
// speedup vs baseline: 1.0726x; 1.0726x over previous
#include <cuda_runtime.h>

// SSIM loss, 7x7 valid window, [32,3,512,512] fp32, scalar out.
// R13 = R9 skeleton (512 thr, merged-phase double buffer, 4-row subchunks,
// register-ring vertical) with fused float4 planes: each staged value is
// (Vx,Vy,Vs,Vxy) in one f4 -> 1 STS.128/row (perm-conflict-free) and the
// horizontal window is 10 LDS.128 per 4 outputs from a single base
// (GSf4=7: 4 data + 3 pad -> odd stride, conflict-free).

#define IW     512
#define OH     506
#define OW     506
#define BR     88
#define NBANDS 6
#define NIMG   96
#define NCTA   (NBANDS * NIMG)      // 576
#define GS4    7                    // f4 per 4-col group (4 data + 3 pad)
#define ROWF4  (128 * GS4)          // 896 f4 per staged row
#define BUFF4  (4 * ROWF4)          // 3584 f4 per buffer (4 rows)
#define SMEM_F4 (2 * BUFF4 + 16)    // + tail pad for last-group halo reads
#define SMEM_BYTES (SMEM_F4 * 16)   // 114,944 B -> 2 CTAs/SM

typedef unsigned long long u64;

__device__ float g_partials[NCTA];
__device__ unsigned int g_count = 0;

__device__ __forceinline__ u64 add2(u64 a, u64 b) {
    u64 r; asm("add.rn.f32x2 %0, %1, %2;" : "=l"(r) : "l"(a), "l"(b)); return r;
}
__device__ __forceinline__ u64 fma2(u64 a, u64 b, u64 c) {
    u64 r; asm("fma.rn.f32x2 %0, %1, %2, %3;" : "=l"(r) : "l"(a), "l"(b), "l"(c)); return r;
}
__device__ __forceinline__ void unpack2(u64 v, float& a, float& b) {
    asm("mov.b64 {%0, %1}, %2;" : "=f"(a), "=f"(b) : "l"(v));
}
#define NEG1X2 0xBF800000BF800000ull

__device__ __forceinline__ float ssim_term(float sx, float sy, float ss, float sxy) {
    const float c1big = 0.2401f;   // 2401 * (0.01)^2
    const float c2big = 2.1168f;   // 2352 * (0.03)^2
    float t1 = sx * sy;
    float a1 = fmaf(t1, 2.0f, c1big);
    float b1 = fmaf(sx, sx, c1big);
    b1 = fmaf(sy, sy, b1);
    float a2 = fmaf(sxy, 98.0f, c2big);
    a2 = fmaf(t1, -2.0f, a2);
    float b2 = fmaf(ss, 49.0f, c2big);
    b2 = fmaf(sx, -sx, b2);
    b2 = fmaf(sy, -sy, b2);
    return __fdividef(a1 * a2, b1 * b2);
}

struct VState {
    float Vx, Vy, Vs, Vxy;
    float rx[8], ry[8];   // ring: slot (PH+j)&7 = departing row at step j
};

template <bool GUARD>
__device__ __forceinline__ void prefetch4(
    const float* __restrict__ xp, const float* __restrict__ yp,
    float* nx, float* ny, int rbn, int rmax, int col) {
#pragma unroll
    for (int j = 0; j < 4; ++j) {
        if (!GUARD || rbn + j <= rmax) {
            nx[j] = xp[(size_t)(rbn + j + 6) * IW + col];
            ny[j] = yp[(size_t)(rbn + j + 6) * IW + col];
        }
    }
}

// Vertical: 4 rows (rb % 8 == PH), per-column running sums, one STS.128/row.
template <int PH, bool GUARD>
__device__ __forceinline__ void vert4(
    VState& v, float4* __restrict__ buf, const float* nx, const float* ny,
    int rb, int rmax, int sidx) {
#pragma unroll
    for (int j = 0; j < 4; ++j) {
        if (!GUARD || rb + j <= rmax) {
            float xn = nx[j], yn = ny[j];
            v.Vx += xn; v.Vy += yn;
            v.Vs  = fmaf(xn, xn, v.Vs);
            v.Vs  = fmaf(yn, yn, v.Vs);
            v.Vxy = fmaf(xn, yn, v.Vxy);
            buf[j * ROWF4 + sidx] = make_float4(v.Vx, v.Vy, v.Vs, v.Vxy);
            float xo = v.rx[(PH + j) & 7];
            float yo = v.ry[(PH + j) & 7];
            v.Vx -= xo; v.Vy -= yo;
            v.Vs  = fmaf(xo, -xo, v.Vs);
            v.Vs  = fmaf(yo, -yo, v.Vs);
            v.Vxy = fmaf(xo, -yo, v.Vxy);
            v.rx[(PH + j + 6) & 7] = xn;
            v.ry[(PH + j + 6) & 7] = yn;
        }
    }
}

// Horizontal: 4 outputs (1 row x 4 cols), 10 conflict-free LDS.128.
// f4 offsets {0,1,2,3, 7,8,9,10, 14,15} = window cols 4G..4G+9.
template <bool GUARD>
__device__ __forceinline__ void horiz4(
    const float4* __restrict__ sb, int rb, int rmax,
    int jrow, int G, float& acc) {
    const int c0 = 4 * G;
    if (c0 >= OW) return;                 // G == 127
    if (GUARD && rb + jrow > rmax) return;

    const ulonglong2* p = (const ulonglong2*)(sb + jrow * ROWF4 + GS4 * G);

    u64 wa[10], wb[10];
    {
        ulonglong2 t0 = p[0], t1 = p[1], t2 = p[2], t3 = p[3];
        ulonglong2 t4 = p[7], t5 = p[8], t6 = p[9], t7 = p[10];
        ulonglong2 t8 = p[14], t9 = p[15];
        wa[0] = t0.x; wb[0] = t0.y;  wa[1] = t1.x; wb[1] = t1.y;
        wa[2] = t2.x; wb[2] = t2.y;  wa[3] = t3.x; wb[3] = t3.y;
        wa[4] = t4.x; wb[4] = t4.y;  wa[5] = t5.x; wb[5] = t5.y;
        wa[6] = t6.x; wb[6] = t6.y;  wa[7] = t7.x; wb[7] = t7.y;
        wa[8] = t8.x; wb[8] = t8.y;  wa[9] = t9.x; wb[9] = t9.y;
    }

    u64 Bout[4];
    {
        u64 B = wa[0];
#pragma unroll
        for (int k = 1; k < 7; ++k) B = add2(B, wa[k]);
        Bout[0] = B;
#pragma unroll
        for (int i = 1; i < 4; ++i) {
            B = add2(B, wa[i + 6]);
            B = fma2(wa[i - 1], NEG1X2, B);
            Bout[i] = B;
        }
    }
    const int T = (OW - c0 < 4) ? (OW - c0) : 4;
    u64 B = wb[0];
#pragma unroll
    for (int k = 1; k < 7; ++k) B = add2(B, wb[k]);
    {
        float sx, sy, ss, sxy;
        unpack2(Bout[0], sx, sy); unpack2(B, ss, sxy);
        acc += ssim_term(sx, sy, ss, sxy);
    }
#pragma unroll
    for (int i = 1; i < 4; ++i) {
        B = add2(B, wb[i + 6]);
        B = fma2(wb[i - 1], NEG1X2, B);
        if (i < T) {
            float sx, sy, ss, sxy;
            unpack2(Bout[i], sx, sy); unpack2(B, ss, sxy);
            acc += ssim_term(sx, sy, ss, sxy);
        }
    }
}

template <bool GUARD>
__device__ __forceinline__ float band_loop(
    const float* __restrict__ xp, const float* __restrict__ yp,
    float4* __restrict__ sm, int r0, int rmax, int tid) {

    // STS.128 conflict-free permutation: lane -> group q = perm8[lane>>2],
    // perm8 = {0,4,1,5,2,6,3,7}; each 8-lane phase stores groups {G, G+4}.
    const int lane = tid & 31;
    const int warp = tid >> 5;
    const int i8   = lane >> 2;
    const int q    = (i8 >> 1) + (i8 & 1) * 4;
    const int r_   = lane & 3;
    const int col  = warp * 32 + q * 4 + r_;
    const int sidx = GS4 * (warp * 8 + q) + r_;    // f4 index within row

    const int jrow = tid >> 7;                     // 0..3
    const int G    = tid & 127;                    // 0..127

    VState v;
    v.Vx = 0.f; v.Vy = 0.f; v.Vs = 0.f; v.Vxy = 0.f;

    // prologue: rows r0..r0+5 -> ring slots 0..5 (phase-0 convention)
#pragma unroll
    for (int k = 0; k < 6; ++k) {
        float x = xp[(size_t)(r0 + k) * IW + col];
        float y = yp[(size_t)(r0 + k) * IW + col];
        v.Vx += x; v.Vy += y;
        v.Vs  = fmaf(x, x, v.Vs);
        v.Vs  = fmaf(y, y, v.Vs);
        v.Vxy = fmaf(x, y, v.Vxy);
        v.rx[k] = x; v.ry[k] = y;
    }

    const int nsub = GUARD ? (((rmax - r0) >> 2) + 1) : (BR / 4);
    float acc = 0.f;

    // subchunk 0 (rows r0..r0+3, always valid)
    {
        float nx[4], ny[4];
        prefetch4<false>(xp, yp, nx, ny, r0, rmax, col);
        vert4<0, false>(v, sm, nx, ny, r0, rmax, sidx);
    }
    __syncthreads();

    for (int t = 0; t + 1 < nsub; t += 2) {
        {   // horizontal(t) + vertical(t+1), rb_next % 8 == 4
            const int rbn = r0 + (t + 1) * 4;
            float nx[4], ny[4];
            prefetch4<GUARD>(xp, yp, nx, ny, rbn, rmax, col);
            horiz4<GUARD>(sm + (size_t)(t & 1) * BUFF4, r0 + t * 4, rmax, jrow, G, acc);
            vert4<4, GUARD>(v, sm + (size_t)((t + 1) & 1) * BUFF4,
                            nx, ny, rbn, rmax, sidx);
            __syncthreads();
        }
        if (t + 2 < nsub) {   // horizontal(t+1) + vertical(t+2), rb_next % 8 == 0
            const int rbn = r0 + (t + 2) * 4;
            float nx[4], ny[4];
            prefetch4<GUARD>(xp, yp, nx, ny, rbn, rmax, col);
            horiz4<GUARD>(sm + (size_t)((t + 1) & 1) * BUFF4, r0 + (t + 1) * 4,
                          rmax, jrow, G, acc);
            vert4<0, GUARD>(v, sm + (size_t)((t + 2) & 1) * BUFF4,
                            nx, ny, rbn, rmax, sidx);
            __syncthreads();
        }
    }
    horiz4<GUARD>(sm + (size_t)((nsub - 1) & 1) * BUFF4, r0 + (nsub - 1) * 4,
                  rmax, jrow, G, acc);
    return acc;
}

__global__ __launch_bounds__(512, 2)
void ssim_kernel(const float* __restrict__ X, const float* __restrict__ Y,
                 float* __restrict__ out) {
    extern __shared__ float4 smbuf[];
    __shared__ float wsum[16];
    __shared__ bool isLast;

    const int tid  = threadIdx.x;
    const int band = blockIdx.x;
    const int img  = blockIdx.y;

    const float* __restrict__ xp = X + (size_t)img * (512 * 512);
    const float* __restrict__ yp = Y + (size_t)img * (512 * 512);
    const int r0   = band * BR;
    const int rmax = min(r0 + BR - 1, OH - 1);

    float acc;
    if (rmax == r0 + BR - 1) {
        acc = band_loop<false>(xp, yp, smbuf, r0, rmax, tid);
    } else {
        acc = band_loop<true>(xp, yp, smbuf, r0, rmax, tid);
    }

    // ---- block reduction ----
#pragma unroll
    for (int o = 16; o > 0; o >>= 1)
        acc += __shfl_xor_sync(0xffffffffu, acc, o);
    if ((tid & 31) == 0) wsum[tid >> 5] = acc;
    __syncthreads();

    if (tid == 0) {
        float s = 0.f;
#pragma unroll
        for (int w = 0; w < 16; ++w) s += wsum[w];
        g_partials[img * NBANDS + band] = s;
        __threadfence();
        unsigned int old = atomicAdd(&g_count, 1u);
        isLast = (old == NCTA - 1);
    }
    __syncthreads();

    // ---- deterministic last-block global reduction ----
    if (isLast) {
        float s = 0.f;
        for (int i = tid; i < NCTA; i += 512) s += g_partials[i];
#pragma unroll
        for (int o = 16; o > 0; o >>= 1)
            s += __shfl_xor_sync(0xffffffffu, s, o);
        if ((tid & 31) == 0) wsum[tid >> 5] = s;
        __syncthreads();
        if (tid == 0) {
            float t = 0.f;
#pragma unroll
            for (int w = 0; w < 16; ++w) t += wsum[w];
            out[0] = 1.0f - t * (1.0f / 24579456.0f);  // 96*506*506
            g_count = 0;  // reset for next graph replay
        }
    }
}

extern "C" void kernel_launch(void* const* d_in, const int* in_sizes, int n_in,
                              void* d_out, int out_size) {
    (void)in_sizes; (void)n_in; (void)out_size;
    const float* X = (const float*)d_in[0];
    const float* Y = (const float*)d_in[1];

    cudaFuncSetAttribute(ssim_kernel,
                         cudaFuncAttributeMaxDynamicSharedMemorySize, SMEM_BYTES);

    dim3 grid(NBANDS, NIMG);
    ssim_kernel<<<grid, 512, SMEM_BYTES>>>(X, Y, (float*)d_out);
}

// round 14
// speedup vs baseline: 1.2316x; 1.1483x over previous
#include <cuda_runtime.h>

// SSIM loss, 7x7 valid window, [32,3,512,512] fp32, scalar out.
// R14 = R9 champion (512 thr, merged-phase double buffer, 4-row subchunks,
// register-ring vertical, GS=6 padded-group conflict-free LDS.128 horizontal,
// permuted conflict-free STS) + instruction diet:
//  - loop-carried global pointers (no per-prefetch IMAD chains)
//  - hoisted smem base pointers for both buffers (horiz + vert)
//  - ssim algebra: a2/b2 derived from a1/b1 (10 -> 8 flops)
//  - T / tail-group predicates hoisted out of the t-loop.

#define IW     512
#define OH     506
#define OW     506
#define BR     88
#define NBANDS 6
#define NIMG   96
#define NCTA   (NBANDS * NIMG)      // 576
#define GS     6                    // float2 per group (4 data + 2 pad)
#define ROWF2  (128 * GS)           // 768 f2 per staged row
#define PLANEF2 (4 * ROWF2)         // 3072
#define BUFF2  (2 * PLANEF2)        // 6144
#define SMEM_F2 (2 * BUFF2 + 16)    // + tail pad for last-group halo reads
#define SMEM_BYTES (SMEM_F2 * 8)    // 98,432 B -> 2 CTAs/SM

typedef unsigned long long u64;

__device__ float g_partials[NCTA];
__device__ unsigned int g_count = 0;

__device__ __forceinline__ u64 add2(u64 a, u64 b) {
    u64 r; asm("add.rn.f32x2 %0, %1, %2;" : "=l"(r) : "l"(a), "l"(b)); return r;
}
__device__ __forceinline__ u64 fma2(u64 a, u64 b, u64 c) {
    u64 r; asm("fma.rn.f32x2 %0, %1, %2, %3;" : "=l"(r) : "l"(a), "l"(b), "l"(c)); return r;
}
__device__ __forceinline__ void unpack2(u64 v, float& a, float& b) {
    asm("mov.b64 {%0, %1}, %2;" : "=f"(a), "=f"(b) : "l"(v));
}
#define NEG1X2 0xBF800000BF800000ull

__device__ __forceinline__ float ssim_term(float sx, float sy, float ss, float sxy) {
    // a1 = 2 sx sy + 2401 C1 ; b1 = sx^2 + sy^2 + 2401 C1
    // a2 = 98 sxy + 2352 C2 - 2 sx sy   = fma(sxy,98,CC) - a1
    // b2 = 49 ss + 2352 C2 - sx^2-sy^2  = fma(ss, 49,CC) - b1
    // CC = 2401 C1 + 2352 C2
    const float c1big = 0.2401f;
    const float CC    = 2.3569f;
    float t1 = sx * sy;
    float a1 = fmaf(t1, 2.0f, c1big);
    float b1 = fmaf(sx, sx, c1big);
    b1 = fmaf(sy, sy, b1);
    float a2 = fmaf(sxy, 98.0f, CC) - a1;
    float b2 = fmaf(ss, 49.0f, CC) - b1;
    return __fdividef(a1 * a2, b1 * b2);
}

struct VState {
    float Vx, Vy, Vs, Vxy;
    float rx[8], ry[8];   // ring: slot (PH+j)&7 = departing row at step j
};

// Prefetch 4 rows from loop-carried pointers (xq/yq point at row rbn+6, col).
template <bool GUARD>
__device__ __forceinline__ void prefetch4(
    const float* __restrict__ xq, const float* __restrict__ yq,
    float* nx, float* ny, int rbn, int rmax) {
#pragma unroll
    for (int j = 0; j < 4; ++j) {
        if (!GUARD || rbn + j <= rmax) {
            nx[j] = xq[j * IW];
            ny[j] = yq[j * IW];
        }
    }
}

// Vertical: 4 rows (rb % 8 == PH); buf already includes sidx.
template <int PH, bool GUARD>
__device__ __forceinline__ void vert4(
    VState& v, float2* __restrict__ buf, const float* nx, const float* ny,
    int rb, int rmax) {
#pragma unroll
    for (int j = 0; j < 4; ++j) {
        if (!GUARD || rb + j <= rmax) {
            float xn = nx[j], yn = ny[j];
            v.Vx += xn; v.Vy += yn;
            v.Vs  = fmaf(xn, xn, v.Vs);
            v.Vs  = fmaf(yn, yn, v.Vs);
            v.Vxy = fmaf(xn, yn, v.Vxy);
            buf[j * ROWF2]           = make_float2(v.Vx, v.Vy);
            buf[PLANEF2 + j * ROWF2] = make_float2(v.Vs, v.Vxy);
            float xo = v.rx[(PH + j) & 7];
            float yo = v.ry[(PH + j) & 7];
            v.Vx -= xo; v.Vy -= yo;
            v.Vs  = fmaf(xo, -xo, v.Vs);
            v.Vs  = fmaf(yo, -yo, v.Vs);
            v.Vxy = fmaf(xo, -yo, v.Vxy);
            v.rx[(PH + j + 6) & 7] = xn;
            v.ry[(PH + j + 6) & 7] = yn;
        }
    }
}

// Load 10 window f2 values via 5 conflict-free LDS.128 (f4 offsets {0,1,3,4,6}).
__device__ __forceinline__ void load_win(const ulonglong2* __restrict__ p, u64* w) {
    ulonglong2 t0 = p[0], t1 = p[1], t2 = p[3], t3 = p[4], t4 = p[6];
    w[0] = t0.x; w[1] = t0.y; w[2] = t1.x; w[3] = t1.y;
    w[4] = t2.x; w[5] = t2.y; w[6] = t3.x; w[7] = t3.y;
    w[8] = t4.x; w[9] = t4.y;
}

// Horizontal: 4 outputs from precomputed plane pointers; ok/T hoisted.
__device__ __forceinline__ void horiz4(
    const ulonglong2* __restrict__ pA, const ulonglong2* __restrict__ pB,
    bool ok, int T, float& acc) {
    if (!ok) return;

    u64 wa[10];
    load_win(pA, wa);
    u64 Bout[4];
    {
        u64 B = wa[0];
#pragma unroll
        for (int k = 1; k < 7; ++k) B = add2(B, wa[k]);
        Bout[0] = B;
#pragma unroll
        for (int i = 1; i < 4; ++i) {
            B = add2(B, wa[i + 6]);
            B = fma2(wa[i - 1], NEG1X2, B);
            Bout[i] = B;
        }
    }
    u64 wb[10];
    load_win(pB, wb);
    u64 B = wb[0];
#pragma unroll
    for (int k = 1; k < 7; ++k) B = add2(B, wb[k]);
    {
        float sx, sy, ss, sxy;
        unpack2(Bout[0], sx, sy); unpack2(B, ss, sxy);
        acc += ssim_term(sx, sy, ss, sxy);
    }
#pragma unroll
    for (int i = 1; i < 4; ++i) {
        B = add2(B, wb[i + 6]);
        B = fma2(wb[i - 1], NEG1X2, B);
        if (i < T) {
            float sx, sy, ss, sxy;
            unpack2(Bout[i], sx, sy); unpack2(B, ss, sxy);
            acc += ssim_term(sx, sy, ss, sxy);
        }
    }
}

template <bool GUARD>
__device__ __forceinline__ float band_loop(
    const float* __restrict__ xp, const float* __restrict__ yp,
    float2* __restrict__ sm, int r0, int rmax, int tid) {

    // STS conflict-free permutation (R9): half-warp 0 -> even groups, 1 -> odd.
    const int lane = tid & 31;
    const int warp = tid >> 5;
    const int q    = (((lane & 15) >> 2) << 1) | (lane >> 4);
    const int r_   = lane & 3;
    const int col  = warp * 32 + q * 4 + r_;
    const int sidx = GS * (warp * 8 + q) + r_;

    const int jrow = tid >> 7;                     // 0..3
    const int g    = tid & 127;                    // 0..127
    const int c0   = 4 * g;
    const bool gok = (c0 < OW);                    // g != 127
    const int T    = (OW - c0 < 4) ? (OW - c0) : 4;

    // Hoisted smem pointers.
    const u64* smq = (const u64*)sm;
    const ulonglong2* hA0 = (const ulonglong2*)(smq + jrow * ROWF2 + GS * g);
    const ulonglong2* hB0 = hA0 + (PLANEF2 / 2);
    const ulonglong2* hA1 = hA0 + (BUFF2 / 2);
    const ulonglong2* hB1 = hA1 + (PLANEF2 / 2);
    float2* s0 = sm + sidx;
    float2* s1 = sm + BUFF2 + sidx;

    VState v;
    v.Vx = 0.f; v.Vy = 0.f; v.Vs = 0.f; v.Vxy = 0.f;

    // prologue: rows r0..r0+5 -> ring slots 0..5
    {
        const float* xpp = xp + (size_t)r0 * IW + col;
        const float* ypp = yp + (size_t)r0 * IW + col;
#pragma unroll
        for (int k = 0; k < 6; ++k) {
            float x = xpp[k * IW];
            float y = ypp[k * IW];
            v.Vx += x; v.Vy += y;
            v.Vs  = fmaf(x, x, v.Vs);
            v.Vs  = fmaf(y, y, v.Vs);
            v.Vxy = fmaf(x, y, v.Vxy);
            v.rx[k] = x; v.ry[k] = y;
        }
    }

    // Loop-carried prefetch pointers (start at row r0+6).
    const float* xq = xp + (size_t)(r0 + 6) * IW + col;
    const float* yq = yp + (size_t)(r0 + 6) * IW + col;

    const int nsub = GUARD ? (((rmax - r0) >> 2) + 1) : (BR / 4);
    float acc = 0.f;

    // subchunk 0 (rows r0..r0+3, always valid)
    {
        float nx[4], ny[4];
        prefetch4<false>(xq, yq, nx, ny, r0, rmax);
        xq += 4 * IW; yq += 4 * IW;
        vert4<0, false>(v, s0, nx, ny, r0, rmax);
    }
    __syncthreads();

    for (int t = 0; t + 1 < nsub; t += 2) {
        {   // horizontal(t, buf0) + vertical(t+1 -> buf1), rb_next % 8 == 4
            const int rbn = r0 + (t + 1) * 4;
            float nx[4], ny[4];
            prefetch4<GUARD>(xq, yq, nx, ny, rbn, rmax);
            xq += 4 * IW; yq += 4 * IW;
            const bool ok = gok && (!GUARD || r0 + t * 4 + jrow <= rmax);
            horiz4(hA0, hB0, ok, T, acc);
            vert4<4, GUARD>(v, s1, nx, ny, rbn, rmax);
            __syncthreads();
        }
        if (t + 2 < nsub) {   // horizontal(t+1, buf1) + vertical(t+2 -> buf0)
            const int rbn = r0 + (t + 2) * 4;
            float nx[4], ny[4];
            prefetch4<GUARD>(xq, yq, nx, ny, rbn, rmax);
            xq += 4 * IW; yq += 4 * IW;
            const bool ok = gok && (!GUARD || r0 + (t + 1) * 4 + jrow <= rmax);
            horiz4(hA1, hB1, ok, T, acc);
            vert4<0, GUARD>(v, s0, nx, ny, rbn, rmax);
            __syncthreads();
        }
    }
    {   // final horizontal
        const bool ok = gok && (!GUARD || r0 + (nsub - 1) * 4 + jrow <= rmax);
        if ((nsub - 1) & 1) horiz4(hA1, hB1, ok, T, acc);
        else                horiz4(hA0, hB0, ok, T, acc);
    }
    return acc;
}

__global__ __launch_bounds__(512, 2)
void ssim_kernel(const float* __restrict__ X, const float* __restrict__ Y,
                 float* __restrict__ out) {
    extern __shared__ float2 smbuf[];
    __shared__ float wsum[16];
    __shared__ bool isLast;

    const int tid  = threadIdx.x;
    const int band = blockIdx.x;
    const int img  = blockIdx.y;

    const float* __restrict__ xp = X + (size_t)img * (512 * 512);
    const float* __restrict__ yp = Y + (size_t)img * (512 * 512);
    const int r0   = band * BR;
    const int rmax = min(r0 + BR - 1, OH - 1);

    float acc;
    if (rmax == r0 + BR - 1) {
        acc = band_loop<false>(xp, yp, smbuf, r0, rmax, tid);
    } else {
        acc = band_loop<true>(xp, yp, smbuf, r0, rmax, tid);
    }

    // ---- block reduction ----
#pragma unroll
    for (int o = 16; o > 0; o >>= 1)
        acc += __shfl_xor_sync(0xffffffffu, acc, o);
    if ((tid & 31) == 0) wsum[tid >> 5] = acc;
    __syncthreads();

    if (tid == 0) {
        float s = 0.f;
#pragma unroll
        for (int w = 0; w < 16; ++w) s += wsum[w];
        g_partials[img * NBANDS + band] = s;
        __threadfence();
        unsigned int old = atomicAdd(&g_count, 1u);
        isLast = (old == NCTA - 1);
    }
    __syncthreads();

    // ---- deterministic last-block global reduction ----
    if (isLast) {
        float s = 0.f;
        for (int i = tid; i < NCTA; i += 512) s += g_partials[i];
#pragma unroll
        for (int o = 16; o > 0; o >>= 1)
            s += __shfl_xor_sync(0xffffffffu, s, o);
        if ((tid & 31) == 0) wsum[tid >> 5] = s;
        __syncthreads();
        if (tid == 0) {
            float t = 0.f;
#pragma unroll
            for (int w = 0; w < 16; ++w) t += wsum[w];
            out[0] = 1.0f - t * (1.0f / 24579456.0f);  // 96*506*506
            g_count = 0;  // reset for next graph replay
        }
    }
}

extern "C" void kernel_launch(void* const* d_in, const int* in_sizes, int n_in,
                              void* d_out, int out_size) {
    (void)in_sizes; (void)n_in; (void)out_size;
    const float* X = (const float*)d_in[0];
    const float* Y = (const float*)d_in[1];

    cudaFuncSetAttribute(ssim_kernel,
                         cudaFuncAttributeMaxDynamicSharedMemorySize, SMEM_BYTES);

    dim3 grid(NBANDS, NIMG);
    ssim_kernel<<<grid, 512, SMEM_BYTES>>>(X, Y, (float*)d_out);
}